// round 1
// baseline (speedup 1.0000x reference)
#include <cuda_runtime.h>
#include <math.h>
#include <stdint.h>
#include <stddef.h>

// Problem dims
#define Bz   4
#define Tz   1024
#define Cz   768
#define Hz   12
#define HDz  64
#define BTz  (Bz*Tz)     // 4096
#define BHz  (Bz*Hz)     // 48

// -------- scratch (static device globals; no allocations allowed) --------
__device__ float g_h   [BTz*Cz];                 // LN1 output
__device__ float g_qkv [BTz*3*Cz];               // qkv
__device__ float g_tab [Tz*HDz];                 // sinusoidal table for delta in [0,1023]
__device__ float g_qtab[(size_t)BHz*Tz*Tz];      // q . table[delta]  (201 MB)
__device__ float g_y   [BTz*Cz];                 // attention out in [B,T,C]
__device__ float g_x1  [BTz*Cz];                 // residual after attention
__device__ float g_h2  [BTz*Cz];                 // LN2 output
__device__ float g_fc  [BTz*4*Cz];               // gelu(fc) activations

// =========================================================================
// Sinusoidal relative-position table: tab[delta][d], delta in [0,1023]
// d<32: sin(delta*invf[d]); d>=32: cos(delta*invf[d-32]); invf[j]=10000^(-2j/64)
// =========================================================================
__global__ void k_tab(float* __restrict__ tab) {
    int idx = blockIdx.x * blockDim.x + threadIdx.x;
    if (idx >= Tz * HDz) return;
    int delta = idx / HDz, d = idx % HDz;
    int j = (d < 32) ? d : d - 32;
    float inv = expf(-logf(10000.f) * (2.f * (float)j) / 64.f);
    float a = (float)delta * inv;
    tab[idx] = (d < 32) ? sinf(a) : cosf(a);
}

// =========================================================================
// LayerNorm (no bias): one block per row, 256 threads, C=768 = 3*256
// =========================================================================
__global__ __launch_bounds__(256)
void k_ln(const float* __restrict__ x, const float* __restrict__ w,
          float* __restrict__ out) {
    __shared__ float red[256];
    int row = blockIdx.x;
    int tid = threadIdx.x;
    const float* xr = x + (size_t)row * Cz;
    float v0 = xr[tid], v1 = xr[tid + 256], v2 = xr[tid + 512];
    red[tid] = v0 + v1 + v2;
    __syncthreads();
    for (int o = 128; o > 0; o >>= 1) {
        if (tid < o) red[tid] += red[tid + o];
        __syncthreads();
    }
    float mean = red[0] * (1.f / Cz);
    __syncthreads();
    float d0 = v0 - mean, d1 = v1 - mean, d2 = v2 - mean;
    red[tid] = d0 * d0 + d1 * d1 + d2 * d2;
    __syncthreads();
    for (int o = 128; o > 0; o >>= 1) {
        if (tid < o) red[tid] += red[tid + o];
        __syncthreads();
    }
    float rstd = rsqrtf(red[0] * (1.f / Cz) + 1e-5f);
    float* orow = out + (size_t)row * Cz;
    orow[tid]       = d0 * rstd * w[tid];
    orow[tid + 256] = d1 * rstd * w[tid + 256];
    orow[tid + 512] = d2 * rstd * w[tid + 512];
}

// =========================================================================
// Generic SGEMM: D = epi(A[M,K] @ B[K,N] (+ Cin))
// 128x128 tile, BK=8, 256 threads, 8x8 per thread.
// EPI: 0=none, 1=add Cin, 2=exact GELU
// M,N multiples of 128; K multiple of 8 (all true for this problem).
// =========================================================================
template <int EPI>
__global__ __launch_bounds__(256)
void k_sgemm(const float* __restrict__ A, const float* __restrict__ Bm,
             const float* __restrict__ Cin, float* __restrict__ D,
             int M, int N, int K) {
    __shared__ float As[8][128];
    __shared__ float Bs[8][128];
    int tid = threadIdx.x;
    int tx = tid & 15, ty = tid >> 4;

    int rowA = (blockIdx.y << 7) + (tid >> 1);
    int aoff = (tid & 1) << 2;
    int colB = (blockIdx.x << 7) + ((tid & 31) << 2);
    const float* Aptr = A + (size_t)rowA * K + aoff;
    const float* Bptr = Bm + (size_t)(tid >> 5) * N + colB;

    float acc[8][8];
#pragma unroll
    for (int i = 0; i < 8; i++)
#pragma unroll
        for (int j = 0; j < 8; j++) acc[i][j] = 0.f;

    for (int k0 = 0; k0 < K; k0 += 8) {
        float4 a4 = *(const float4*)(Aptr + k0);
        float4 b4 = *(const float4*)(Bptr + (size_t)k0 * N);
        int ra = tid >> 1;
        As[aoff + 0][ra] = a4.x;
        As[aoff + 1][ra] = a4.y;
        As[aoff + 2][ra] = a4.z;
        As[aoff + 3][ra] = a4.w;
        *(float4*)&Bs[tid >> 5][(tid & 31) << 2] = b4;
        __syncthreads();
#pragma unroll
        for (int kk = 0; kk < 8; kk++) {
            float4 a0 = *(float4*)&As[kk][ty << 3];
            float4 a1 = *(float4*)&As[kk][(ty << 3) + 4];
            float4 b0 = *(float4*)&Bs[kk][tx << 3];
            float4 b1 = *(float4*)&Bs[kk][(tx << 3) + 4];
            float ar[8] = {a0.x, a0.y, a0.z, a0.w, a1.x, a1.y, a1.z, a1.w};
            float br[8] = {b0.x, b0.y, b0.z, b0.w, b1.x, b1.y, b1.z, b1.w};
#pragma unroll
            for (int i = 0; i < 8; i++)
#pragma unroll
                for (int j = 0; j < 8; j++) acc[i][j] = fmaf(ar[i], br[j], acc[i][j]);
        }
        __syncthreads();
    }

    int r0 = (blockIdx.y << 7) + (ty << 3);
    int c0 = (blockIdx.x << 7) + (tx << 3);
#pragma unroll
    for (int i = 0; i < 8; i++) {
        size_t base = (size_t)(r0 + i) * N + c0;
#pragma unroll
        for (int j = 0; j < 8; j++) {
            float v = acc[i][j];
            if (EPI == 1) v += Cin[base + j];
            if (EPI == 2) v = 0.5f * v * (1.f + erff(v * 0.70710678118654752f));
            D[base + j] = v;
        }
    }
}

// =========================================================================
// Qtab GEMM: qtab[bh, i, delta] = sum_d q[b,i,h,d] * tab[delta,d]
// grid (BH, 16 i-tiles, 16 delta-tiles), only dt<=it computed (causal band).
// 64x64x64 tile, 256 threads, 4x4 per thread.
// =========================================================================
__global__ __launch_bounds__(256)
void k_qtab(const float* __restrict__ qkv, const float* __restrict__ tab,
            float* __restrict__ qtab) {
    int bh = blockIdx.x;
    int it = blockIdx.y;
    int dt = blockIdx.z;
    if (dt > it) return;
    int b = bh / Hz, h = bh % Hz;

    __shared__ float Qs[64 * 64];  // [d][i]
    __shared__ float Ts[64 * 64];  // [d][u]

    int tid = threadIdx.x;
    {
        int i = tid >> 2;
        int d4 = (tid & 3) << 2;
        const float* src = qkv + (size_t)(b * Tz + it * 64 + i) * (3 * Cz) + h * HDz;
        const float* ts  = tab + (size_t)(dt * 64 + i) * HDz;
#pragma unroll
        for (int t = 0; t < 64; t += 16) {
            int d = d4 + t;
            float4 v = *(const float4*)(src + d);
            Qs[(d + 0) * 64 + i] = v.x;
            Qs[(d + 1) * 64 + i] = v.y;
            Qs[(d + 2) * 64 + i] = v.z;
            Qs[(d + 3) * 64 + i] = v.w;
            float4 w = *(const float4*)(ts + d);
            Ts[(d + 0) * 64 + i] = w.x;
            Ts[(d + 1) * 64 + i] = w.y;
            Ts[(d + 2) * 64 + i] = w.z;
            Ts[(d + 3) * 64 + i] = w.w;
        }
    }
    __syncthreads();

    int tx = tid & 15, ty = tid >> 4;
    float acc[4][4];
#pragma unroll
    for (int a = 0; a < 4; a++)
#pragma unroll
        for (int c = 0; c < 4; c++) acc[a][c] = 0.f;

#pragma unroll 16
    for (int d = 0; d < 64; d++) {
        float4 q4 = *(float4*)&Qs[d * 64 + (ty << 2)];
        float4 t4 = *(float4*)&Ts[d * 64 + (tx << 2)];
        float q[4] = {q4.x, q4.y, q4.z, q4.w};
        float t[4] = {t4.x, t4.y, t4.z, t4.w};
#pragma unroll
        for (int a = 0; a < 4; a++)
#pragma unroll
            for (int c = 0; c < 4; c++) acc[a][c] = fmaf(q[a], t[c], acc[a][c]);
    }

#pragma unroll
    for (int a = 0; a < 4; a++) {
        int i = it * 64 + (ty << 2) + a;
        size_t base = ((size_t)bh * Tz + i) * Tz + dt * 64 + (tx << 2);
        *(float4*)&qtab[base] = make_float4(acc[a][0], acc[a][1], acc[a][2], acc[a][3]);
    }
}

// =========================================================================
// Fused causal attention with relative-position scores, streaming softmax.
// grid (BH, 16 query tiles), 256 threads. Static smem = exactly 48 KB.
// Online softmax is register-resident with 16-lane shfl reductions.
// =========================================================================
__global__ __launch_bounds__(256)
void k_attn(const float* __restrict__ qkv, const float* __restrict__ qtab,
            float* __restrict__ y) {
    __shared__ float Qs[64 * 64];  // [d][i]
    __shared__ float KV[64 * 64];  // K phase: [d][j]; V phase: [j][d]
    __shared__ float Ss[64 * 64];  // P tile [i][j]

    int bh = blockIdx.x, it = blockIdx.y;
    int b = bh / Hz, h = bh % Hz;
    int i0 = it * 64;
    int tid = threadIdx.x;
    int tx = tid & 15, ty = tid >> 4;

    // load Q tile transposed
    {
        int i = tid >> 2;
        int d4 = (tid & 3) << 2;
        const float* src = qkv + (size_t)(b * Tz + i0 + i) * (3 * Cz) + h * HDz;
#pragma unroll
        for (int t = 0; t < 64; t += 16) {
            int d = d4 + t;
            float4 v = *(const float4*)(src + d);
            Qs[(d + 0) * 64 + i] = v.x;
            Qs[(d + 1) * 64 + i] = v.y;
            Qs[(d + 2) * 64 + i] = v.z;
            Qs[(d + 3) * 64 + i] = v.w;
        }
    }

    float O[4][4];
    float m_run[4], l_run[4];
#pragma unroll
    for (int a = 0; a < 4; a++) {
        m_run[a] = -1e30f;
        l_run[a] = 0.f;
#pragma unroll
        for (int c = 0; c < 4; c++) O[a][c] = 0.f;
    }

    const float* qt_base = qtab + (size_t)bh * Tz * Tz;

    for (int jt = 0; jt <= it; jt++) {
        int j0 = jt * 64;
        __syncthreads();  // prev AV done with KV/Ss; Q load done (first iter)
        // load K tile transposed: KV[d][j]
        {
            int j = tid >> 2;
            int d4 = (tid & 3) << 2;
            const float* src = qkv + (size_t)(b * Tz + j0 + j) * (3 * Cz) + Cz + h * HDz;
#pragma unroll
            for (int t = 0; t < 64; t += 16) {
                int d = d4 + t;
                float4 v = *(const float4*)(src + d);
                KV[(d + 0) * 64 + j] = v.x;
                KV[(d + 1) * 64 + j] = v.y;
                KV[(d + 2) * 64 + j] = v.z;
                KV[(d + 3) * 64 + j] = v.w;
            }
        }
        __syncthreads();

        // scores s = Q K^T
        float s[4][4];
#pragma unroll
        for (int a = 0; a < 4; a++)
#pragma unroll
            for (int c = 0; c < 4; c++) s[a][c] = 0.f;
#pragma unroll 16
        for (int d = 0; d < 64; d++) {
            float4 q4 = *(float4*)&Qs[d * 64 + (ty << 2)];
            float4 k4 = *(float4*)&KV[d * 64 + (tx << 2)];
            float q[4] = {q4.x, q4.y, q4.z, q4.w};
            float kk[4] = {k4.x, k4.y, k4.z, k4.w};
#pragma unroll
            for (int a = 0; a < 4; a++)
#pragma unroll
                for (int c = 0; c < 4; c++) s[a][c] = fmaf(q[a], kk[c], s[a][c]);
        }

        // + relative-position term, scale, causal mask
#pragma unroll
        for (int a = 0; a < 4; a++) {
            int i = i0 + (ty << 2) + a;
            const float* qrow = qt_base + (size_t)i * Tz;
#pragma unroll
            for (int c = 0; c < 4; c++) {
                int j = j0 + (tx << 2) + c;
                if (j > i)
                    s[a][c] = -1e30f;
                else
                    s[a][c] = (s[a][c] + qrow[i - j]) * 0.125f;
            }
        }

        // online softmax (register + 16-lane shfl over tx group)
#pragma unroll
        for (int a = 0; a < 4; a++) {
            float mt = fmaxf(fmaxf(s[a][0], s[a][1]), fmaxf(s[a][2], s[a][3]));
#pragma unroll
            for (int k = 1; k < 16; k <<= 1)
                mt = fmaxf(mt, __shfl_xor_sync(0xffffffffu, mt, k));
            float mnew = fmaxf(m_run[a], mt);
            float al = expf(m_run[a] - mnew);
            m_run[a] = mnew;
            float ls = 0.f;
#pragma unroll
            for (int c = 0; c < 4; c++) {
                float p = expf(s[a][c] - mnew);
                s[a][c] = p;
                ls += p;
            }
#pragma unroll
            for (int k = 1; k < 16; k <<= 1)
                ls += __shfl_xor_sync(0xffffffffu, ls, k);
            l_run[a] = l_run[a] * al + ls;
#pragma unroll
            for (int c = 0; c < 4; c++) O[a][c] *= al;
        }

        // write P to smem
#pragma unroll
        for (int a = 0; a < 4; a++)
            *(float4*)&Ss[((ty << 2) + a) * 64 + (tx << 2)] =
                make_float4(s[a][0], s[a][1], s[a][2], s[a][3]);

        __syncthreads();  // scores GEMM done reading K; P visible

        // load V tile: KV[j][d]
        {
            int j = tid >> 2;
            int d4 = (tid & 3) << 2;
            const float* src = qkv + (size_t)(b * Tz + j0 + j) * (3 * Cz) + 2 * Cz + h * HDz;
#pragma unroll
            for (int t = 0; t < 64; t += 16) {
                float4 v = *(const float4*)(src + d4 + t);
                *(float4*)&KV[j * 64 + d4 + t] = v;
            }
        }
        __syncthreads();

        // O += P @ V
#pragma unroll 8
        for (int j = 0; j < 64; j++) {
            float p[4];
#pragma unroll
            for (int a = 0; a < 4; a++) p[a] = Ss[((ty << 2) + a) * 64 + j];
            float4 v4 = *(float4*)&KV[j * 64 + (tx << 2)];
            float vv[4] = {v4.x, v4.y, v4.z, v4.w};
#pragma unroll
            for (int a = 0; a < 4; a++)
#pragma unroll
                for (int c = 0; c < 4; c++) O[a][c] = fmaf(p[a], vv[c], O[a][c]);
        }
    }

    // normalize + write out in [B,T,C]
#pragma unroll
    for (int a = 0; a < 4; a++) {
        int i = i0 + (ty << 2) + a;
        float inv = 1.f / l_run[a];
        float* dst = y + (size_t)(b * Tz + i) * Cz + h * HDz + (tx << 2);
        *(float4*)dst = make_float4(O[a][0] * inv, O[a][1] * inv, O[a][2] * inv,
                                    O[a][3] * inv);
    }
}

// =========================================================================
// launcher
// =========================================================================
extern "C" void kernel_launch(void* const* d_in, const int* in_sizes, int n_in,
                              void* d_out, int out_size) {
    const float* x       = (const float*)d_in[0];
    const float* ln1_w   = (const float*)d_in[1];
    const float* w_attn  = (const float*)d_in[2];
    // d_in[3] = w_pos : dead code in the reference, intentionally unused
    const float* w_cproj = (const float*)d_in[4];
    const float* ln2_w   = (const float*)d_in[5];
    const float* w_fc    = (const float*)d_in[6];
    const float* w_mproj = (const float*)d_in[7];
    float* out = (float*)d_out;

    float *h, *qkv, *tab, *qtab, *y, *x1, *h2, *fc;
    cudaGetSymbolAddress((void**)&h, g_h);
    cudaGetSymbolAddress((void**)&qkv, g_qkv);
    cudaGetSymbolAddress((void**)&tab, g_tab);
    cudaGetSymbolAddress((void**)&qtab, g_qtab);
    cudaGetSymbolAddress((void**)&y, g_y);
    cudaGetSymbolAddress((void**)&x1, g_x1);
    cudaGetSymbolAddress((void**)&h2, g_h2);
    cudaGetSymbolAddress((void**)&fc, g_fc);

    // sinusoidal table
    k_tab<<<(Tz * HDz + 255) / 256, 256>>>(tab);
    // LN1
    k_ln<<<BTz, 256>>>(x, ln1_w, h);
    // qkv = h @ w_attn   [4096 x 2304]
    k_sgemm<0><<<dim3((3 * Cz) / 128, BTz / 128), 256>>>(h, w_attn, nullptr, qkv,
                                                         BTz, 3 * Cz, Cz);
    // qtab = q @ tab^T (causal band only)
    k_qtab<<<dim3(BHz, 16, 16), 256>>>(qkv, tab, qtab);
    // fused attention
    k_attn<<<dim3(BHz, 16), 256>>>(qkv, qtab, y);
    // x1 = x + y @ w_cproj
    k_sgemm<1><<<dim3(Cz / 128, BTz / 128), 256>>>(y, w_cproj, x, x1, BTz, Cz, Cz);
    // LN2
    k_ln<<<BTz, 256>>>(x1, ln2_w, h2);
    // fc = gelu(h2 @ w_fc)   [4096 x 3072]
    k_sgemm<2><<<dim3((4 * Cz) / 128, BTz / 128), 256>>>(h2, w_fc, nullptr, fc,
                                                         BTz, 4 * Cz, Cz);
    // out = x1 + fc @ w_mproj
    k_sgemm<1><<<dim3(Cz / 128, BTz / 128), 256>>>(fc, w_mproj, x1, out, BTz, Cz,
                                                   4 * Cz);
}

// round 4
// speedup vs baseline: 1.7120x; 1.7120x over previous
#include <cuda_runtime.h>
#include <cuda_bf16.h>
#include <math.h>
#include <stdint.h>
#include <stddef.h>

// Problem dims
#define Bz   4
#define Tz   1024
#define Cz   768
#define Hz   12
#define HDz  64
#define BTz  (Bz*Tz)     // 4096
#define BHz  (Bz*Hz)     // 48

// -------- scratch (static device globals; no allocations allowed) --------
__device__ float g_h   [BTz*Cz];
__device__ float g_qkv [BTz*3*Cz];
__device__ float g_tab [Tz*HDz];
__device__ float g_qtab[(size_t)BHz*Tz*Tz];
__device__ float g_y   [BTz*Cz];
__device__ float g_x1  [BTz*Cz];
__device__ float g_h2  [BTz*Cz];
__device__ float g_fc  [BTz*4*Cz];

// transposed + bf16-split weights: [N,K] layout, hi and lo parts
#define WT_TOTAL 7077888
#define WT_ATTN  0
#define WT_CPROJ 1769472
#define WT_FC    2359296
#define WT_MPROJ 4718592
__device__ __nv_bfloat16 g_bt_hi[WT_TOTAL];
__device__ __nv_bfloat16 g_bt_lo[WT_TOTAL];

// =========================================================================
// mma.sync m16n8k16 bf16 (row.col), fp32 accum
// =========================================================================
__device__ __forceinline__ void mma16816(float* c, const uint32_t* a,
                                         const uint32_t* b) {
    asm volatile(
        "mma.sync.aligned.m16n8k16.row.col.f32.bf16.bf16.f32 "
        "{%0,%1,%2,%3}, {%4,%5,%6,%7}, {%8,%9}, {%0,%1,%2,%3};"
        : "+f"(c[0]), "+f"(c[1]), "+f"(c[2]), "+f"(c[3])
        : "r"(a[0]), "r"(a[1]), "r"(a[2]), "r"(a[3]), "r"(b[0]), "r"(b[1]));
}

// =========================================================================
// weight transpose + bf16 hi/lo split: src[K,N] -> dst_hi/lo[N,K]
// =========================================================================
__global__ __launch_bounds__(256)
void k_tsplit(const float* __restrict__ src, __nv_bfloat16* __restrict__ hi,
              __nv_bfloat16* __restrict__ lo, int K, int N) {
    __shared__ float t[32][33];
    int k0 = blockIdx.x * 32, n0 = blockIdx.y * 32;
    int tx = threadIdx.x & 31, ty = threadIdx.x >> 5;  // 32 x 8
#pragma unroll
    for (int r = 0; r < 32; r += 8)
        t[ty + r][tx] = src[(size_t)(k0 + ty + r) * N + n0 + tx];
    __syncthreads();
#pragma unroll
    for (int r = 0; r < 32; r += 8) {
        float v = t[tx][ty + r];
        __nv_bfloat16 h = __float2bfloat16(v);
        size_t o = (size_t)(n0 + ty + r) * K + k0 + tx;
        hi[o] = h;
        lo[o] = __float2bfloat16(v - __bfloat162float(h));
    }
}

// =========================================================================
// bf16x3 tensor-core GEMM: D = epi(A[M,K] @ W[K,N] (+Cin))
// W given as Bt[N,K] bf16 hi/lo. 128x128 CTA tile, BK=32, 8 warps (32x64 each).
// EPI: 0 none, 1 +Cin, 2 exact GELU
// =========================================================================
#define PITCH 40   // bf16 elems per smem row (80B): bank-conflict-free frags

template <int EPI>
__global__ __launch_bounds__(256, 2)
void k_mma(const float* __restrict__ A, const __nv_bfloat16* __restrict__ Bth,
           const __nv_bfloat16* __restrict__ Btl, const float* __restrict__ Cin,
           float* __restrict__ D, int M, int N, int K) {
    __shared__ __nv_bfloat16 sAh[128 * PITCH];
    __shared__ __nv_bfloat16 sAl[128 * PITCH];
    __shared__ __nv_bfloat16 sBh[128 * PITCH];
    __shared__ __nv_bfloat16 sBl[128 * PITCH];

    const int tid = threadIdx.x;
    const int wid = tid >> 5, lane = tid & 31;
    const int wm = wid & 3;   // 0..3 -> 32-row block
    const int wn = wid >> 2;  // 0..1 -> 64-col block
    const int m0 = blockIdx.y << 7, n0 = blockIdx.x << 7;
    const int gq = lane >> 2;        // lane/4
    const int kq = (lane & 3) << 1;  // (lane%4)*2

    float acc[2][8][4];
#pragma unroll
    for (int mi = 0; mi < 2; mi++)
#pragma unroll
        for (int ni = 0; ni < 8; ni++)
#pragma unroll
            for (int j = 0; j < 4; j++) acc[mi][ni][j] = 0.f;

    const int lr = tid >> 1;          // 0..127 (tile row)
    const int lc = (tid & 1) << 4;    // 0 or 16 (tile col)

    for (int k0 = 0; k0 < K; k0 += 32) {
        __syncthreads();
        // ---- A: load f32, split into bf16 hi/lo ----
        {
            const float* ap = A + (size_t)(m0 + lr) * K + k0 + lc;
#pragma unroll
            for (int j = 0; j < 16; j += 8) {
                float4 v0 = *(const float4*)(ap + j);
                float4 v1 = *(const float4*)(ap + j + 4);
                __nv_bfloat162 h0 = __floats2bfloat162_rn(v0.x, v0.y);
                __nv_bfloat162 h1 = __floats2bfloat162_rn(v0.z, v0.w);
                __nv_bfloat162 h2 = __floats2bfloat162_rn(v1.x, v1.y);
                __nv_bfloat162 h3 = __floats2bfloat162_rn(v1.z, v1.w);
                __nv_bfloat162 l0 = __floats2bfloat162_rn(
                    v0.x - __bfloat162float(h0.x), v0.y - __bfloat162float(h0.y));
                __nv_bfloat162 l1 = __floats2bfloat162_rn(
                    v0.z - __bfloat162float(h1.x), v0.w - __bfloat162float(h1.y));
                __nv_bfloat162 l2 = __floats2bfloat162_rn(
                    v1.x - __bfloat162float(h2.x), v1.y - __bfloat162float(h2.y));
                __nv_bfloat162 l3 = __floats2bfloat162_rn(
                    v1.z - __bfloat162float(h3.x), v1.w - __bfloat162float(h3.y));
                uint4 hh = make_uint4(*(uint32_t*)&h0, *(uint32_t*)&h1,
                                      *(uint32_t*)&h2, *(uint32_t*)&h3);
                uint4 ll = make_uint4(*(uint32_t*)&l0, *(uint32_t*)&l1,
                                      *(uint32_t*)&l2, *(uint32_t*)&l3);
                *(uint4*)&sAh[lr * PITCH + lc + j] = hh;
                *(uint4*)&sAl[lr * PITCH + lc + j] = ll;
            }
        }
        // ---- B: copy bf16 hi/lo ----
        {
            const __nv_bfloat16* bp = Bth + (size_t)(n0 + lr) * K + k0 + lc;
            *(uint4*)&sBh[lr * PITCH + lc]     = *(const uint4*)(bp);
            *(uint4*)&sBh[lr * PITCH + lc + 8] = *(const uint4*)(bp + 8);
            const __nv_bfloat16* lp = Btl + (size_t)(n0 + lr) * K + k0 + lc;
            *(uint4*)&sBl[lr * PITCH + lc]     = *(const uint4*)(lp);
            *(uint4*)&sBl[lr * PITCH + lc + 8] = *(const uint4*)(lp + 8);
        }
        __syncthreads();

#pragma unroll
        for (int ko = 0; ko < 32; ko += 16) {
            uint32_t bh[8][2], bl[8][2];
#pragma unroll
            for (int ni = 0; ni < 8; ni++) {
                int row = wn * 64 + ni * 8 + gq;
                bh[ni][0] = *(const uint32_t*)&sBh[row * PITCH + ko + kq];
                bh[ni][1] = *(const uint32_t*)&sBh[row * PITCH + ko + kq + 8];
                bl[ni][0] = *(const uint32_t*)&sBl[row * PITCH + ko + kq];
                bl[ni][1] = *(const uint32_t*)&sBl[row * PITCH + ko + kq + 8];
            }
#pragma unroll
            for (int mi = 0; mi < 2; mi++) {
                int r0 = wm * 32 + mi * 16 + gq;
                uint32_t ah[4], al[4];
                ah[0] = *(const uint32_t*)&sAh[r0 * PITCH + ko + kq];
                ah[1] = *(const uint32_t*)&sAh[(r0 + 8) * PITCH + ko + kq];
                ah[2] = *(const uint32_t*)&sAh[r0 * PITCH + ko + kq + 8];
                ah[3] = *(const uint32_t*)&sAh[(r0 + 8) * PITCH + ko + kq + 8];
                al[0] = *(const uint32_t*)&sAl[r0 * PITCH + ko + kq];
                al[1] = *(const uint32_t*)&sAl[(r0 + 8) * PITCH + ko + kq];
                al[2] = *(const uint32_t*)&sAl[r0 * PITCH + ko + kq + 8];
                al[3] = *(const uint32_t*)&sAl[(r0 + 8) * PITCH + ko + kq + 8];
#pragma unroll
                for (int ni = 0; ni < 8; ni++) {
                    mma16816(acc[mi][ni], ah, bh[ni]);
                    mma16816(acc[mi][ni], ah, bl[ni]);
                    mma16816(acc[mi][ni], al, bh[ni]);
                }
            }
        }
    }

    // ---- epilogue ----
#pragma unroll
    for (int mi = 0; mi < 2; mi++) {
#pragma unroll
        for (int ni = 0; ni < 8; ni++) {
#pragma unroll
            for (int half = 0; half < 2; half++) {
                int r = m0 + wm * 32 + mi * 16 + gq + half * 8;
                int cc = n0 + wn * 64 + ni * 8 + kq;
                size_t o = (size_t)r * N + cc;
                float2 v;
                v.x = acc[mi][ni][half * 2 + 0];
                v.y = acc[mi][ni][half * 2 + 1];
                if (EPI == 1) {
                    float2 ci = *(const float2*)(Cin + o);
                    v.x += ci.x;
                    v.y += ci.y;
                }
                if (EPI == 2) {
                    v.x = 0.5f * v.x * (1.f + erff(v.x * 0.70710678118654752f));
                    v.y = 0.5f * v.y * (1.f + erff(v.y * 0.70710678118654752f));
                }
                *(float2*)(D + o) = v;
            }
        }
    }
}

// =========================================================================
// Sinusoidal relative-position table
// =========================================================================
__global__ void k_tab(float* __restrict__ tab) {
    int idx = blockIdx.x * blockDim.x + threadIdx.x;
    if (idx >= Tz * HDz) return;
    int delta = idx / HDz, d = idx % HDz;
    int j = (d < 32) ? d : d - 32;
    float inv = expf(-logf(10000.f) * (2.f * (float)j) / 64.f);
    float a = (float)delta * inv;
    tab[idx] = (d < 32) ? sinf(a) : cosf(a);
}

// =========================================================================
// LayerNorm
// =========================================================================
__global__ __launch_bounds__(256)
void k_ln(const float* __restrict__ x, const float* __restrict__ w,
          float* __restrict__ out) {
    __shared__ float red[256];
    int row = blockIdx.x;
    int tid = threadIdx.x;
    const float* xr = x + (size_t)row * Cz;
    float v0 = xr[tid], v1 = xr[tid + 256], v2 = xr[tid + 512];
    red[tid] = v0 + v1 + v2;
    __syncthreads();
    for (int o = 128; o > 0; o >>= 1) {
        if (tid < o) red[tid] += red[tid + o];
        __syncthreads();
    }
    float mean = red[0] * (1.f / Cz);
    __syncthreads();
    float d0 = v0 - mean, d1 = v1 - mean, d2 = v2 - mean;
    red[tid] = d0 * d0 + d1 * d1 + d2 * d2;
    __syncthreads();
    for (int o = 128; o > 0; o >>= 1) {
        if (tid < o) red[tid] += red[tid + o];
        __syncthreads();
    }
    float rstd = rsqrtf(red[0] * (1.f / Cz) + 1e-5f);
    float* orow = out + (size_t)row * Cz;
    orow[tid]       = d0 * rstd * w[tid];
    orow[tid + 256] = d1 * rstd * w[tid + 256];
    orow[tid + 512] = d2 * rstd * w[tid + 512];
}

// =========================================================================
// Qtab GEMM: qtab[bh,i,delta] = q[b,i,h,:] . tab[delta,:]  (causal band only)
// =========================================================================
__global__ __launch_bounds__(256)
void k_qtab(const float* __restrict__ qkv, const float* __restrict__ tab,
            float* __restrict__ qtab) {
    int bh = blockIdx.x;
    int it = blockIdx.y;
    int dt = blockIdx.z;
    if (dt > it) return;
    int b = bh / Hz, h = bh % Hz;

    __shared__ float Qs[64 * 64];
    __shared__ float Ts[64 * 64];

    int tid = threadIdx.x;
    {
        int i = tid >> 2;
        int d4 = (tid & 3) << 2;
        const float* src = qkv + (size_t)(b * Tz + it * 64 + i) * (3 * Cz) + h * HDz;
        const float* ts  = tab + (size_t)(dt * 64 + i) * HDz;
#pragma unroll
        for (int t = 0; t < 64; t += 16) {
            int d = d4 + t;
            float4 v = *(const float4*)(src + d);
            Qs[(d + 0) * 64 + i] = v.x;
            Qs[(d + 1) * 64 + i] = v.y;
            Qs[(d + 2) * 64 + i] = v.z;
            Qs[(d + 3) * 64 + i] = v.w;
            float4 w = *(const float4*)(ts + d);
            Ts[(d + 0) * 64 + i] = w.x;
            Ts[(d + 1) * 64 + i] = w.y;
            Ts[(d + 2) * 64 + i] = w.z;
            Ts[(d + 3) * 64 + i] = w.w;
        }
    }
    __syncthreads();

    int tx = tid & 15, ty = tid >> 4;
    float acc[4][4];
#pragma unroll
    for (int a = 0; a < 4; a++)
#pragma unroll
        for (int c = 0; c < 4; c++) acc[a][c] = 0.f;

#pragma unroll 16
    for (int d = 0; d < 64; d++) {
        float4 q4 = *(float4*)&Qs[d * 64 + (ty << 2)];
        float4 t4 = *(float4*)&Ts[d * 64 + (tx << 2)];
        float q[4] = {q4.x, q4.y, q4.z, q4.w};
        float t[4] = {t4.x, t4.y, t4.z, t4.w};
#pragma unroll
        for (int a = 0; a < 4; a++)
#pragma unroll
            for (int c = 0; c < 4; c++) acc[a][c] = fmaf(q[a], t[c], acc[a][c]);
    }

#pragma unroll
    for (int a = 0; a < 4; a++) {
        int i = it * 64 + (ty << 2) + a;
        size_t base = ((size_t)bh * Tz + i) * Tz + dt * 64 + (tx << 2);
        *(float4*)&qtab[base] = make_float4(acc[a][0], acc[a][1], acc[a][2], acc[a][3]);
    }
}

// =========================================================================
// Fused causal attention with rel-pos scores, streaming softmax
// =========================================================================
__global__ __launch_bounds__(256)
void k_attn(const float* __restrict__ qkv, const float* __restrict__ qtab,
            float* __restrict__ y) {
    __shared__ float Qs[64 * 64];
    __shared__ float KV[64 * 64];
    __shared__ float Ss[64 * 64];

    int bh = blockIdx.x, it = blockIdx.y;
    int b = bh / Hz, h = bh % Hz;
    int i0 = it * 64;
    int tid = threadIdx.x;
    int tx = tid & 15, ty = tid >> 4;

    {
        int i = tid >> 2;
        int d4 = (tid & 3) << 2;
        const float* src = qkv + (size_t)(b * Tz + i0 + i) * (3 * Cz) + h * HDz;
#pragma unroll
        for (int t = 0; t < 64; t += 16) {
            int d = d4 + t;
            float4 v = *(const float4*)(src + d);
            Qs[(d + 0) * 64 + i] = v.x;
            Qs[(d + 1) * 64 + i] = v.y;
            Qs[(d + 2) * 64 + i] = v.z;
            Qs[(d + 3) * 64 + i] = v.w;
        }
    }

    float O[4][4];
    float m_run[4], l_run[4];
#pragma unroll
    for (int a = 0; a < 4; a++) {
        m_run[a] = -1e30f;
        l_run[a] = 0.f;
#pragma unroll
        for (int c = 0; c < 4; c++) O[a][c] = 0.f;
    }

    const float* qt_base = qtab + (size_t)bh * Tz * Tz;

    for (int jt = 0; jt <= it; jt++) {
        int j0 = jt * 64;
        __syncthreads();
        {
            int j = tid >> 2;
            int d4 = (tid & 3) << 2;
            const float* src = qkv + (size_t)(b * Tz + j0 + j) * (3 * Cz) + Cz + h * HDz;
#pragma unroll
            for (int t = 0; t < 64; t += 16) {
                int d = d4 + t;
                float4 v = *(const float4*)(src + d);
                KV[(d + 0) * 64 + j] = v.x;
                KV[(d + 1) * 64 + j] = v.y;
                KV[(d + 2) * 64 + j] = v.z;
                KV[(d + 3) * 64 + j] = v.w;
            }
        }
        __syncthreads();

        float s[4][4];
#pragma unroll
        for (int a = 0; a < 4; a++)
#pragma unroll
            for (int c = 0; c < 4; c++) s[a][c] = 0.f;
#pragma unroll 16
        for (int d = 0; d < 64; d++) {
            float4 q4 = *(float4*)&Qs[d * 64 + (ty << 2)];
            float4 k4 = *(float4*)&KV[d * 64 + (tx << 2)];
            float q[4] = {q4.x, q4.y, q4.z, q4.w};
            float kk[4] = {k4.x, k4.y, k4.z, k4.w};
#pragma unroll
            for (int a = 0; a < 4; a++)
#pragma unroll
                for (int c = 0; c < 4; c++) s[a][c] = fmaf(q[a], kk[c], s[a][c]);
        }

#pragma unroll
        for (int a = 0; a < 4; a++) {
            int i = i0 + (ty << 2) + a;
            const float* qrow = qt_base + (size_t)i * Tz;
#pragma unroll
            for (int c = 0; c < 4; c++) {
                int j = j0 + (tx << 2) + c;
                if (j > i)
                    s[a][c] = -1e30f;
                else
                    s[a][c] = (s[a][c] + qrow[i - j]) * 0.125f;
            }
        }

#pragma unroll
        for (int a = 0; a < 4; a++) {
            float mt = fmaxf(fmaxf(s[a][0], s[a][1]), fmaxf(s[a][2], s[a][3]));
#pragma unroll
            for (int k = 1; k < 16; k <<= 1)
                mt = fmaxf(mt, __shfl_xor_sync(0xffffffffu, mt, k));
            float mnew = fmaxf(m_run[a], mt);
            float al = expf(m_run[a] - mnew);
            m_run[a] = mnew;
            float ls = 0.f;
#pragma unroll
            for (int c = 0; c < 4; c++) {
                float p = expf(s[a][c] - mnew);
                s[a][c] = p;
                ls += p;
            }
#pragma unroll
            for (int k = 1; k < 16; k <<= 1)
                ls += __shfl_xor_sync(0xffffffffu, ls, k);
            l_run[a] = l_run[a] * al + ls;
#pragma unroll
            for (int c = 0; c < 4; c++) O[a][c] *= al;
        }

#pragma unroll
        for (int a = 0; a < 4; a++)
            *(float4*)&Ss[((ty << 2) + a) * 64 + (tx << 2)] =
                make_float4(s[a][0], s[a][1], s[a][2], s[a][3]);

        __syncthreads();

        {
            int j = tid >> 2;
            int d4 = (tid & 3) << 2;
            const float* src = qkv + (size_t)(b * Tz + j0 + j) * (3 * Cz) + 2 * Cz + h * HDz;
#pragma unroll
            for (int t = 0; t < 64; t += 16) {
                float4 v = *(const float4*)(src + d4 + t);
                *(float4*)&KV[j * 64 + d4 + t] = v;
            }
        }
        __syncthreads();

#pragma unroll 8
        for (int j = 0; j < 64; j++) {
            float p[4];
#pragma unroll
            for (int a = 0; a < 4; a++) p[a] = Ss[((ty << 2) + a) * 64 + j];
            float4 v4 = *(float4*)&KV[j * 64 + (tx << 2)];
            float vv[4] = {v4.x, v4.y, v4.z, v4.w};
#pragma unroll
            for (int a = 0; a < 4; a++)
#pragma unroll
                for (int c = 0; c < 4; c++) O[a][c] = fmaf(p[a], vv[c], O[a][c]);
        }
    }

#pragma unroll
    for (int a = 0; a < 4; a++) {
        int i = i0 + (ty << 2) + a;
        float inv = 1.f / l_run[a];
        float* dst = y + (size_t)(b * Tz + i) * Cz + h * HDz + (tx << 2);
        *(float4*)dst = make_float4(O[a][0] * inv, O[a][1] * inv, O[a][2] * inv,
                                    O[a][3] * inv);
    }
}

// =========================================================================
// launcher
// =========================================================================
extern "C" void kernel_launch(void* const* d_in, const int* in_sizes, int n_in,
                              void* d_out, int out_size) {
    const float* x       = (const float*)d_in[0];
    const float* ln1_w   = (const float*)d_in[1];
    const float* w_attn  = (const float*)d_in[2];
    // d_in[3] = w_pos : dead code in the reference
    const float* w_cproj = (const float*)d_in[4];
    const float* ln2_w   = (const float*)d_in[5];
    const float* w_fc    = (const float*)d_in[6];
    const float* w_mproj = (const float*)d_in[7];
    float* out = (float*)d_out;

    float *h, *qkv, *tab, *qtab, *y, *x1, *h2, *fc;
    __nv_bfloat16 *bth, *btl;
    cudaGetSymbolAddress((void**)&h, g_h);
    cudaGetSymbolAddress((void**)&qkv, g_qkv);
    cudaGetSymbolAddress((void**)&tab, g_tab);
    cudaGetSymbolAddress((void**)&qtab, g_qtab);
    cudaGetSymbolAddress((void**)&y, g_y);
    cudaGetSymbolAddress((void**)&x1, g_x1);
    cudaGetSymbolAddress((void**)&h2, g_h2);
    cudaGetSymbolAddress((void**)&fc, g_fc);
    cudaGetSymbolAddress((void**)&bth, g_bt_hi);
    cudaGetSymbolAddress((void**)&btl, g_bt_lo);

    // weight preprocessing (transpose + bf16 split)
    k_tsplit<<<dim3(Cz / 32, (3 * Cz) / 32), 256>>>(w_attn, bth + WT_ATTN, btl + WT_ATTN, Cz, 3 * Cz);
    k_tsplit<<<dim3(Cz / 32, Cz / 32), 256>>>(w_cproj, bth + WT_CPROJ, btl + WT_CPROJ, Cz, Cz);
    k_tsplit<<<dim3(Cz / 32, (4 * Cz) / 32), 256>>>(w_fc, bth + WT_FC, btl + WT_FC, Cz, 4 * Cz);
    k_tsplit<<<dim3((4 * Cz) / 32, Cz / 32), 256>>>(w_mproj, bth + WT_MPROJ, btl + WT_MPROJ, 4 * Cz, Cz);

    // sinusoidal table + LN1
    k_tab<<<(Tz * HDz + 255) / 256, 256>>>(tab);
    k_ln<<<BTz, 256>>>(x, ln1_w, h);

    // qkv = h @ w_attn
    k_mma<0><<<dim3((3 * Cz) / 128, BTz / 128), 256>>>(
        h, bth + WT_ATTN, btl + WT_ATTN, nullptr, qkv, BTz, 3 * Cz, Cz);
    // qtab
    k_qtab<<<dim3(BHz, 16, 16), 256>>>(qkv, tab, qtab);
    // fused attention
    k_attn<<<dim3(BHz, 16), 256>>>(qkv, qtab, y);
    // x1 = x + y @ w_cproj
    k_mma<1><<<dim3(Cz / 128, BTz / 128), 256>>>(
        y, bth + WT_CPROJ, btl + WT_CPROJ, x, x1, BTz, Cz, Cz);
    // LN2
    k_ln<<<BTz, 256>>>(x1, ln2_w, h2);
    // fc = gelu(h2 @ w_fc)
    k_mma<2><<<dim3((4 * Cz) / 128, BTz / 128), 256>>>(
        h2, bth + WT_FC, btl + WT_FC, nullptr, fc, BTz, 4 * Cz, Cz);
    // out = x1 + fc @ w_mproj
    k_mma<1><<<dim3(Cz / 128, BTz / 128), 256>>>(
        fc, bth + WT_MPROJ, btl + WT_MPROJ, x1, out, BTz, Cz, 4 * Cz);
}

// round 6
// speedup vs baseline: 1.8942x; 1.1064x over previous
#include <cuda_runtime.h>
#include <cuda_bf16.h>
#include <math.h>
#include <stdint.h>
#include <stddef.h>

// Problem dims
#define Bz   4
#define Tz   1024
#define Cz   768
#define Hz   12
#define HDz  64
#define BTz  (Bz*Tz)     // 4096
#define BHz  (Bz*Hz)     // 48

// -------- scratch (static device globals; no allocations allowed) --------
__device__ float g_h   [BTz*Cz];                    // LN1 out
__device__ __nv_bfloat16 g_qkvh[BTz*3*Cz];          // qkv bf16 hi
__device__ __nv_bfloat16 g_qkvl[BTz*3*Cz];          // qkv bf16 lo
__device__ __nv_bfloat16 g_tabh[Tz*HDz];            // sinus table hi
__device__ __nv_bfloat16 g_tabl[Tz*HDz];            // sinus table lo
__device__ float g_qtab[(size_t)BHz*Tz*Tz];         // q . table[delta]
__device__ float g_y   [BTz*Cz];
__device__ float g_x1  [BTz*Cz];
__device__ float g_h2  [BTz*Cz];
__device__ float g_fc  [BTz*4*Cz];

// transposed + bf16-split weights: [N,K] layout, hi and lo parts
#define WT_TOTAL 7077888
#define WT_ATTN  0
#define WT_CPROJ 1769472
#define WT_FC    2359296
#define WT_MPROJ 4718592
__device__ __nv_bfloat16 g_bt_hi[WT_TOTAL];
__device__ __nv_bfloat16 g_bt_lo[WT_TOTAL];

// =========================================================================
// mma.sync m16n8k16 bf16 (row.col), fp32 accum
// =========================================================================
__device__ __forceinline__ void mma16816(float* c, const uint32_t* a,
                                         const uint32_t* b) {
    asm volatile(
        "mma.sync.aligned.m16n8k16.row.col.f32.bf16.bf16.f32 "
        "{%0,%1,%2,%3}, {%4,%5,%6,%7}, {%8,%9}, {%0,%1,%2,%3};"
        : "+f"(c[0]), "+f"(c[1]), "+f"(c[2]), "+f"(c[3])
        : "r"(a[0]), "r"(a[1]), "r"(a[2]), "r"(a[3]), "r"(b[0]), "r"(b[1]));
}

// fast exp2 on the FMA pipe (t <= 0 expected; clamp keeps denormals away)
__device__ __forceinline__ float fexp2(float t) {
    t = fmaxf(t, -80.f);
    int i = __float2int_rn(t);
    float r = t - (float)i;  // [-0.5, 0.5]
    float q = 1.5403530e-4f;
    q = fmaf(q, r, 1.3333558e-3f);
    q = fmaf(q, r, 9.6181291e-3f);
    q = fmaf(q, r, 5.5504109e-2f);
    q = fmaf(q, r, 2.4022651e-1f);
    q = fmaf(q, r, 6.9314718e-1f);
    q = fmaf(q, r, 1.0f);
    return q * __int_as_float((i + 127) << 23);
}
// exp((s-m)*0.125) = 2^((s-m)*CE)
#define CEXP 0.18033688011112042f

// =========================================================================
// weight transpose + bf16 hi/lo split: src[K,N] -> dst_hi/lo[N,K]
// =========================================================================
__global__ __launch_bounds__(256)
void k_tsplit(const float* __restrict__ src, __nv_bfloat16* __restrict__ hi,
              __nv_bfloat16* __restrict__ lo, int K, int N) {
    __shared__ float t[32][33];
    int k0 = blockIdx.x * 32, n0 = blockIdx.y * 32;
    int tx = threadIdx.x & 31, ty = threadIdx.x >> 5;
#pragma unroll
    for (int r = 0; r < 32; r += 8)
        t[ty + r][tx] = src[(size_t)(k0 + ty + r) * N + n0 + tx];
    __syncthreads();
#pragma unroll
    for (int r = 0; r < 32; r += 8) {
        float v = t[tx][ty + r];
        __nv_bfloat16 h = __float2bfloat16(v);
        size_t o = (size_t)(n0 + ty + r) * K + k0 + tx;
        hi[o] = h;
        lo[o] = __float2bfloat16(v - __bfloat162float(h));
    }
}

// =========================================================================
// bf16x3 tensor-core GEMM: D = epi(A[M,K] @ W[K,N] (+Cin))
// EPI: 0 none, 1 +Cin, 2 exact GELU, 3 write bf16 hi/lo pair arrays
// =========================================================================
#define PITCH 40

template <int EPI>
__global__ __launch_bounds__(256, 2)
void k_mma(const float* __restrict__ A, const __nv_bfloat16* __restrict__ Bth,
           const __nv_bfloat16* __restrict__ Btl, const float* __restrict__ Cin,
           float* __restrict__ D, __nv_bfloat16* __restrict__ Dh,
           __nv_bfloat16* __restrict__ Dl, int M, int N, int K) {
    __shared__ __nv_bfloat16 sAh[128 * PITCH];
    __shared__ __nv_bfloat16 sAl[128 * PITCH];
    __shared__ __nv_bfloat16 sBh[128 * PITCH];
    __shared__ __nv_bfloat16 sBl[128 * PITCH];

    const int tid = threadIdx.x;
    const int wid = tid >> 5, lane = tid & 31;
    const int wm = wid & 3;
    const int wn = wid >> 2;
    const int m0 = blockIdx.y << 7, n0 = blockIdx.x << 7;
    const int gq = lane >> 2;
    const int kq = (lane & 3) << 1;

    float acc[2][8][4];
#pragma unroll
    for (int mi = 0; mi < 2; mi++)
#pragma unroll
        for (int ni = 0; ni < 8; ni++)
#pragma unroll
            for (int j = 0; j < 4; j++) acc[mi][ni][j] = 0.f;

    const int lr = tid >> 1;
    const int lc = (tid & 1) << 4;

    for (int k0 = 0; k0 < K; k0 += 32) {
        __syncthreads();
        {
            const float* ap = A + (size_t)(m0 + lr) * K + k0 + lc;
#pragma unroll
            for (int j = 0; j < 16; j += 8) {
                float4 v0 = *(const float4*)(ap + j);
                float4 v1 = *(const float4*)(ap + j + 4);
                __nv_bfloat162 h0 = __floats2bfloat162_rn(v0.x, v0.y);
                __nv_bfloat162 h1 = __floats2bfloat162_rn(v0.z, v0.w);
                __nv_bfloat162 h2 = __floats2bfloat162_rn(v1.x, v1.y);
                __nv_bfloat162 h3 = __floats2bfloat162_rn(v1.z, v1.w);
                __nv_bfloat162 l0 = __floats2bfloat162_rn(
                    v0.x - __bfloat162float(h0.x), v0.y - __bfloat162float(h0.y));
                __nv_bfloat162 l1 = __floats2bfloat162_rn(
                    v0.z - __bfloat162float(h1.x), v0.w - __bfloat162float(h1.y));
                __nv_bfloat162 l2 = __floats2bfloat162_rn(
                    v1.x - __bfloat162float(h2.x), v1.y - __bfloat162float(h2.y));
                __nv_bfloat162 l3 = __floats2bfloat162_rn(
                    v1.z - __bfloat162float(h3.x), v1.w - __bfloat162float(h3.y));
                uint4 hh = make_uint4(*(uint32_t*)&h0, *(uint32_t*)&h1,
                                      *(uint32_t*)&h2, *(uint32_t*)&h3);
                uint4 ll = make_uint4(*(uint32_t*)&l0, *(uint32_t*)&l1,
                                      *(uint32_t*)&l2, *(uint32_t*)&l3);
                *(uint4*)&sAh[lr * PITCH + lc + j] = hh;
                *(uint4*)&sAl[lr * PITCH + lc + j] = ll;
            }
        }
        {
            const __nv_bfloat16* bp = Bth + (size_t)(n0 + lr) * K + k0 + lc;
            *(uint4*)&sBh[lr * PITCH + lc]     = *(const uint4*)(bp);
            *(uint4*)&sBh[lr * PITCH + lc + 8] = *(const uint4*)(bp + 8);
            const __nv_bfloat16* lp = Btl + (size_t)(n0 + lr) * K + k0 + lc;
            *(uint4*)&sBl[lr * PITCH + lc]     = *(const uint4*)(lp);
            *(uint4*)&sBl[lr * PITCH + lc + 8] = *(const uint4*)(lp + 8);
        }
        __syncthreads();

#pragma unroll
        for (int ko = 0; ko < 32; ko += 16) {
            uint32_t bh[8][2], bl[8][2];
#pragma unroll
            for (int ni = 0; ni < 8; ni++) {
                int row = wn * 64 + ni * 8 + gq;
                bh[ni][0] = *(const uint32_t*)&sBh[row * PITCH + ko + kq];
                bh[ni][1] = *(const uint32_t*)&sBh[row * PITCH + ko + kq + 8];
                bl[ni][0] = *(const uint32_t*)&sBl[row * PITCH + ko + kq];
                bl[ni][1] = *(const uint32_t*)&sBl[row * PITCH + ko + kq + 8];
            }
#pragma unroll
            for (int mi = 0; mi < 2; mi++) {
                int r0 = wm * 32 + mi * 16 + gq;
                uint32_t ah[4], al[4];
                ah[0] = *(const uint32_t*)&sAh[r0 * PITCH + ko + kq];
                ah[1] = *(const uint32_t*)&sAh[(r0 + 8) * PITCH + ko + kq];
                ah[2] = *(const uint32_t*)&sAh[r0 * PITCH + ko + kq + 8];
                ah[3] = *(const uint32_t*)&sAh[(r0 + 8) * PITCH + ko + kq + 8];
                al[0] = *(const uint32_t*)&sAl[r0 * PITCH + ko + kq];
                al[1] = *(const uint32_t*)&sAl[(r0 + 8) * PITCH + ko + kq];
                al[2] = *(const uint32_t*)&sAl[r0 * PITCH + ko + kq + 8];
                al[3] = *(const uint32_t*)&sAl[(r0 + 8) * PITCH + ko + kq + 8];
#pragma unroll
                for (int ni = 0; ni < 8; ni++) {
                    mma16816(acc[mi][ni], ah, bh[ni]);
                    mma16816(acc[mi][ni], ah, bl[ni]);
                    mma16816(acc[mi][ni], al, bh[ni]);
                }
            }
        }
    }

#pragma unroll
    for (int mi = 0; mi < 2; mi++) {
#pragma unroll
        for (int ni = 0; ni < 8; ni++) {
#pragma unroll
            for (int half = 0; half < 2; half++) {
                int r = m0 + wm * 32 + mi * 16 + gq + half * 8;
                int cc = n0 + wn * 64 + ni * 8 + kq;
                size_t o = (size_t)r * N + cc;
                float2 v;
                v.x = acc[mi][ni][half * 2 + 0];
                v.y = acc[mi][ni][half * 2 + 1];
                if (EPI == 1) {
                    float2 ci = *(const float2*)(Cin + o);
                    v.x += ci.x;
                    v.y += ci.y;
                }
                if (EPI == 2) {
                    v.x = 0.5f * v.x * (1.f + erff(v.x * 0.70710678118654752f));
                    v.y = 0.5f * v.y * (1.f + erff(v.y * 0.70710678118654752f));
                }
                if (EPI == 3) {
                    __nv_bfloat162 hh = __floats2bfloat162_rn(v.x, v.y);
                    __nv_bfloat162 ll = __floats2bfloat162_rn(
                        v.x - __bfloat162float(hh.x), v.y - __bfloat162float(hh.y));
                    *(uint32_t*)&Dh[o] = *(uint32_t*)&hh;
                    *(uint32_t*)&Dl[o] = *(uint32_t*)&ll;
                } else {
                    *(float2*)(D + o) = v;
                }
            }
        }
    }
}

// =========================================================================
// Sinusoidal table -> bf16 hi/lo
// =========================================================================
__global__ void k_tab(__nv_bfloat16* __restrict__ th,
                      __nv_bfloat16* __restrict__ tl) {
    int idx = blockIdx.x * blockDim.x + threadIdx.x;
    if (idx >= Tz * HDz) return;
    int delta = idx / HDz, d = idx % HDz;
    int j = (d < 32) ? d : d - 32;
    float inv = expf(-logf(10000.f) * (2.f * (float)j) / 64.f);
    float a = (float)delta * inv;
    float v = (d < 32) ? sinf(a) : cosf(a);
    __nv_bfloat16 h = __float2bfloat16(v);
    th[idx] = h;
    tl[idx] = __float2bfloat16(v - __bfloat162float(h));
}

// =========================================================================
// LayerNorm
// =========================================================================
__global__ __launch_bounds__(256)
void k_ln(const float* __restrict__ x, const float* __restrict__ w,
          float* __restrict__ out) {
    __shared__ float red[256];
    int row = blockIdx.x;
    int tid = threadIdx.x;
    const float* xr = x + (size_t)row * Cz;
    float v0 = xr[tid], v1 = xr[tid + 256], v2 = xr[tid + 512];
    red[tid] = v0 + v1 + v2;
    __syncthreads();
    for (int o = 128; o > 0; o >>= 1) {
        if (tid < o) red[tid] += red[tid + o];
        __syncthreads();
    }
    float mean = red[0] * (1.f / Cz);
    __syncthreads();
    float d0 = v0 - mean, d1 = v1 - mean, d2 = v2 - mean;
    red[tid] = d0 * d0 + d1 * d1 + d2 * d2;
    __syncthreads();
    for (int o = 128; o > 0; o >>= 1) {
        if (tid < o) red[tid] += red[tid + o];
        __syncthreads();
    }
    float rstd = rsqrtf(red[0] * (1.f / Cz) + 1e-5f);
    float* orow = out + (size_t)row * Cz;
    orow[tid]       = d0 * rstd * w[tid];
    orow[tid + 256] = d1 * rstd * w[tid + 256];
    orow[tid + 512] = d2 * rstd * w[tid + 512];
}

// =========================================================================
// qtab via mma: qtab[bh,i,delta] = q[b,i,h,:] . tab[delta,:]  (dt<=it only)
// 128 thr / 4 warps, each warp one m16 of the 64-row i tile.
// =========================================================================
#define AP 72  // smem pitch (bf16) for attention-side tiles

__global__ __launch_bounds__(128)
void k_qtabm(const __nv_bfloat16* __restrict__ qkvh,
             const __nv_bfloat16* __restrict__ qkvl,
             const __nv_bfloat16* __restrict__ tabh,
             const __nv_bfloat16* __restrict__ tabl,
             float* __restrict__ qtab) {
    int bh = blockIdx.x;
    int it = gridDim.y - 1 - blockIdx.y;
    int dt = blockIdx.z;
    if (dt > it) return;
    int b = bh / Hz, h = bh % Hz;

    __shared__ __nv_bfloat16 sQh[64 * AP], sQl[64 * AP];
    __shared__ __nv_bfloat16 sTh[64 * AP], sTl[64 * AP];

    int tid = threadIdx.x;
    int wid = tid >> 5, lane = tid & 31;
    int gq = lane >> 2, kq = (lane & 3) << 1;

    {
        int r = tid >> 1, cb = (tid & 1) << 5;
        const __nv_bfloat16* qh =
            qkvh + (size_t)(b * Tz + it * 64 + r) * (3 * Cz) + h * HDz + cb;
        const __nv_bfloat16* ql =
            qkvl + (size_t)(b * Tz + it * 64 + r) * (3 * Cz) + h * HDz + cb;
#pragma unroll
        for (int j = 0; j < 32; j += 8) {
            *(uint4*)&sQh[r * AP + cb + j] = *(const uint4*)(qh + j);
            *(uint4*)&sQl[r * AP + cb + j] = *(const uint4*)(ql + j);
        }
        const __nv_bfloat16* th = tabh + (size_t)(dt * 64 + r) * HDz + cb;
        const __nv_bfloat16* tl = tabl + (size_t)(dt * 64 + r) * HDz + cb;
#pragma unroll
        for (int j = 0; j < 32; j += 8) {
            *(uint4*)&sTh[r * AP + cb + j] = *(const uint4*)(th + j);
            *(uint4*)&sTl[r * AP + cb + j] = *(const uint4*)(tl + j);
        }
    }
    __syncthreads();

    float S[8][4];
#pragma unroll
    for (int ni = 0; ni < 8; ni++)
#pragma unroll
        for (int j = 0; j < 4; j++) S[ni][j] = 0.f;

#pragma unroll
    for (int kt = 0; kt < 4; kt++) {
        int r0 = wid * 16 + gq, ko = kt * 16;
        uint32_t ah[4], al[4];
        ah[0] = *(const uint32_t*)&sQh[r0 * AP + ko + kq];
        ah[1] = *(const uint32_t*)&sQh[(r0 + 8) * AP + ko + kq];
        ah[2] = *(const uint32_t*)&sQh[r0 * AP + ko + kq + 8];
        ah[3] = *(const uint32_t*)&sQh[(r0 + 8) * AP + ko + kq + 8];
        al[0] = *(const uint32_t*)&sQl[r0 * AP + ko + kq];
        al[1] = *(const uint32_t*)&sQl[(r0 + 8) * AP + ko + kq];
        al[2] = *(const uint32_t*)&sQl[r0 * AP + ko + kq + 8];
        al[3] = *(const uint32_t*)&sQl[(r0 + 8) * AP + ko + kq + 8];
#pragma unroll
        for (int ni = 0; ni < 8; ni++) {
            int row = ni * 8 + gq;
            uint32_t bh[2], bl[2];
            bh[0] = *(const uint32_t*)&sTh[row * AP + ko + kq];
            bh[1] = *(const uint32_t*)&sTh[row * AP + ko + kq + 8];
            bl[0] = *(const uint32_t*)&sTl[row * AP + ko + kq];
            bl[1] = *(const uint32_t*)&sTl[row * AP + ko + kq + 8];
            mma16816(S[ni], ah, bh);
            mma16816(S[ni], ah, bl);
            mma16816(S[ni], al, bh);
        }
    }

    int ia = it * 64 + wid * 16 + gq;
#pragma unroll
    for (int ni = 0; ni < 8; ni++) {
        int col = dt * 64 + ni * 8 + kq;
        size_t oa = ((size_t)bh * Tz + ia) * Tz + col;
        *(float2*)&qtab[oa] = make_float2(S[ni][0], S[ni][1]);
        size_t ob = ((size_t)bh * Tz + ia + 8) * Tz + col;
        *(float2*)&qtab[ob] = make_float2(S[ni][2], S[ni][3]);
    }
}

// =========================================================================
// Tensor-core fused causal attention, 64-row query tile, 4 warps.
// Score: Q K^T (bf16x3) + qtab gather; softmax in fragment layout (poly exp2);
// P.V via in-register fragment conversion (bf16x3).
// =========================================================================
__global__ __launch_bounds__(128)
void k_attnm(const __nv_bfloat16* __restrict__ qkvh,
             const __nv_bfloat16* __restrict__ qkvl,
             const float* __restrict__ qtab, float* __restrict__ y) {
    __shared__ __nv_bfloat16 sQh[64 * AP], sQl[64 * AP];
    __shared__ __nv_bfloat16 sKh[64 * AP], sKl[64 * AP];  // K, then V^T

    int bh = blockIdx.x;
    int it = gridDim.y - 1 - blockIdx.y;
    int b = bh / Hz, h = bh % Hz;
    int i0 = it * 64;
    int tid = threadIdx.x;
    int wid = tid >> 5, lane = tid & 31;
    int gq = lane >> 2, kq = (lane & 3) << 1;

    // load Q tile (bf16 hi/lo)
    {
        int r = tid >> 1, cb = (tid & 1) << 5;
        const __nv_bfloat16* qh =
            qkvh + (size_t)(b * Tz + i0 + r) * (3 * Cz) + h * HDz + cb;
        const __nv_bfloat16* ql =
            qkvl + (size_t)(b * Tz + i0 + r) * (3 * Cz) + h * HDz + cb;
#pragma unroll
        for (int j = 0; j < 32; j += 8) {
            *(uint4*)&sQh[r * AP + cb + j] = *(const uint4*)(qh + j);
            *(uint4*)&sQl[r * AP + cb + j] = *(const uint4*)(ql + j);
        }
    }
    __syncthreads();

    // Q fragments in registers (fixed for whole block row)
    uint32_t aQh[4][4], aQl[4][4];
#pragma unroll
    for (int kt = 0; kt < 4; kt++) {
        int r0 = wid * 16 + gq, ko = kt * 16;
        aQh[kt][0] = *(const uint32_t*)&sQh[r0 * AP + ko + kq];
        aQh[kt][1] = *(const uint32_t*)&sQh[(r0 + 8) * AP + ko + kq];
        aQh[kt][2] = *(const uint32_t*)&sQh[r0 * AP + ko + kq + 8];
        aQh[kt][3] = *(const uint32_t*)&sQh[(r0 + 8) * AP + ko + kq + 8];
        aQl[kt][0] = *(const uint32_t*)&sQl[r0 * AP + ko + kq];
        aQl[kt][1] = *(const uint32_t*)&sQl[(r0 + 8) * AP + ko + kq];
        aQl[kt][2] = *(const uint32_t*)&sQl[r0 * AP + ko + kq + 8];
        aQl[kt][3] = *(const uint32_t*)&sQl[(r0 + 8) * AP + ko + kq + 8];
    }

    float O[8][4];
#pragma unroll
    for (int ni = 0; ni < 8; ni++)
#pragma unroll
        for (int j = 0; j < 4; j++) O[ni][j] = 0.f;
    float m_a = -1e30f, m_b = -1e30f, l_a = 0.f, l_b = 0.f;

    const float* qt0 = qtab + (size_t)bh * Tz * Tz;
    const int ia = i0 + wid * 16 + gq;  // row for c0,c1
    const int ib = ia + 8;              // row for c2,c3

    for (int jt = 0; jt <= it; jt++) {
        int j0 = jt * 64;
        __syncthreads();  // prior PV reads done
        // ---- load K tile (rows j, cols d) hi/lo ----
        {
            int r = tid >> 1, cb = (tid & 1) << 5;
            const __nv_bfloat16* kh =
                qkvh + (size_t)(b * Tz + j0 + r) * (3 * Cz) + Cz + h * HDz + cb;
            const __nv_bfloat16* kl =
                qkvl + (size_t)(b * Tz + j0 + r) * (3 * Cz) + Cz + h * HDz + cb;
#pragma unroll
            for (int j = 0; j < 32; j += 8) {
                *(uint4*)&sKh[r * AP + cb + j] = *(const uint4*)(kh + j);
                *(uint4*)&sKl[r * AP + cb + j] = *(const uint4*)(kl + j);
            }
        }
        __syncthreads();

        // ---- scores ----
        float S[8][4];
#pragma unroll
        for (int ni = 0; ni < 8; ni++)
#pragma unroll
            for (int j = 0; j < 4; j++) S[ni][j] = 0.f;
#pragma unroll
        for (int kt = 0; kt < 4; kt++) {
            int ko = kt * 16;
#pragma unroll
            for (int ni = 0; ni < 8; ni++) {
                int row = ni * 8 + gq;
                uint32_t bh[2], bl[2];
                bh[0] = *(const uint32_t*)&sKh[row * AP + ko + kq];
                bh[1] = *(const uint32_t*)&sKh[row * AP + ko + kq + 8];
                bl[0] = *(const uint32_t*)&sKl[row * AP + ko + kq];
                bl[1] = *(const uint32_t*)&sKl[row * AP + ko + kq + 8];
                mma16816(S[ni], aQh[kt], bh);
                mma16816(S[ni], aQh[kt], bl);
                mma16816(S[ni], aQl[kt], bh);
            }
        }

        // ---- rel-pos add + causal mask ----
        bool diag = (jt == it);
#pragma unroll
        for (int ni = 0; ni < 8; ni++) {
            int jbase = j0 + ni * 8 + kq;
#pragma unroll
            for (int c = 0; c < 4; c++) {
                int row = (c < 2) ? ia : ib;
                int j = jbase + (c & 1);
                if (diag && j > row)
                    S[ni][c] = -1e30f;
                else
                    S[ni][c] += qt0[(size_t)row * Tz + (row - j)];
            }
        }

        // ---- online softmax (rows a: c0,c1 ; rows b: c2,c3) ----
        float mt_a = -1e30f, mt_b = -1e30f;
#pragma unroll
        for (int ni = 0; ni < 8; ni++) {
            mt_a = fmaxf(mt_a, fmaxf(S[ni][0], S[ni][1]));
            mt_b = fmaxf(mt_b, fmaxf(S[ni][2], S[ni][3]));
        }
        mt_a = fmaxf(mt_a, __shfl_xor_sync(0xffffffffu, mt_a, 1));
        mt_a = fmaxf(mt_a, __shfl_xor_sync(0xffffffffu, mt_a, 2));
        mt_b = fmaxf(mt_b, __shfl_xor_sync(0xffffffffu, mt_b, 1));
        mt_b = fmaxf(mt_b, __shfl_xor_sync(0xffffffffu, mt_b, 2));
        float mn_a = fmaxf(m_a, mt_a), mn_b = fmaxf(m_b, mt_b);
        float al_a = fexp2((m_a - mn_a) * CEXP);
        float al_b = fexp2((m_b - mn_b) * CEXP);
        m_a = mn_a;
        m_b = mn_b;
        float sum_a = 0.f, sum_b = 0.f;
#pragma unroll
        for (int ni = 0; ni < 8; ni++) {
            float p0 = fexp2((S[ni][0] - mn_a) * CEXP);
            float p1 = fexp2((S[ni][1] - mn_a) * CEXP);
            float p2 = fexp2((S[ni][2] - mn_b) * CEXP);
            float p3 = fexp2((S[ni][3] - mn_b) * CEXP);
            S[ni][0] = p0; S[ni][1] = p1; S[ni][2] = p2; S[ni][3] = p3;
            sum_a += p0 + p1;
            sum_b += p2 + p3;
        }
        sum_a += __shfl_xor_sync(0xffffffffu, sum_a, 1);
        sum_a += __shfl_xor_sync(0xffffffffu, sum_a, 2);
        sum_b += __shfl_xor_sync(0xffffffffu, sum_b, 1);
        sum_b += __shfl_xor_sync(0xffffffffu, sum_b, 2);
        l_a = l_a * al_a + sum_a;
        l_b = l_b * al_b + sum_b;
#pragma unroll
        for (int ni = 0; ni < 8; ni++) {
            O[ni][0] *= al_a;
            O[ni][1] *= al_a;
            O[ni][2] *= al_b;
            O[ni][3] *= al_b;
        }

        __syncthreads();  // score reads of K done
        // ---- load V tile transposed [d][j] hi/lo ----
        {
            const size_t vbase =
                (size_t)(b * Tz + j0) * (3 * Cz) + 2 * Cz + h * HDz;
#pragma unroll
            for (int n = 0; n < 8; n++) {
                int u = n * 128 + tid;
                int j = (u >> 5) << 1;  // 0,2,..,62
                int d = (u & 31) << 1;  // 0,2,..,62
                const __nv_bfloat16* sh = qkvh + vbase + (size_t)j * (3 * Cz) + d;
                uint32_t va = *(const uint32_t*)sh;
                uint32_t vb = *(const uint32_t*)(sh + 3 * Cz);
                *(uint32_t*)&sKh[d * AP + j] = __byte_perm(va, vb, 0x5410);
                *(uint32_t*)&sKh[(d + 1) * AP + j] = __byte_perm(va, vb, 0x7632);
                const __nv_bfloat16* sl = qkvl + vbase + (size_t)j * (3 * Cz) + d;
                va = *(const uint32_t*)sl;
                vb = *(const uint32_t*)(sl + 3 * Cz);
                *(uint32_t*)&sKl[d * AP + j] = __byte_perm(va, vb, 0x5410);
                *(uint32_t*)&sKl[(d + 1) * AP + j] = __byte_perm(va, vb, 0x7632);
            }
        }
        __syncthreads();

        // ---- O += P @ V  (P fragments built in registers) ----
#pragma unroll
        for (int kt = 0; kt < 4; kt++) {
            int ko = kt * 16;
            uint32_t aPh[4], aPl[4];
            {
                __nv_bfloat162 h0 = __floats2bfloat162_rn(S[2 * kt][0], S[2 * kt][1]);
                __nv_bfloat162 h1 = __floats2bfloat162_rn(S[2 * kt][2], S[2 * kt][3]);
                __nv_bfloat162 h2 =
                    __floats2bfloat162_rn(S[2 * kt + 1][0], S[2 * kt + 1][1]);
                __nv_bfloat162 h3 =
                    __floats2bfloat162_rn(S[2 * kt + 1][2], S[2 * kt + 1][3]);
                __nv_bfloat162 l0 = __floats2bfloat162_rn(
                    S[2 * kt][0] - __bfloat162float(h0.x),
                    S[2 * kt][1] - __bfloat162float(h0.y));
                __nv_bfloat162 l1 = __floats2bfloat162_rn(
                    S[2 * kt][2] - __bfloat162float(h1.x),
                    S[2 * kt][3] - __bfloat162float(h1.y));
                __nv_bfloat162 l2 = __floats2bfloat162_rn(
                    S[2 * kt + 1][0] - __bfloat162float(h2.x),
                    S[2 * kt + 1][1] - __bfloat162float(h2.y));
                __nv_bfloat162 l3 = __floats2bfloat162_rn(
                    S[2 * kt + 1][2] - __bfloat162float(h3.x),
                    S[2 * kt + 1][3] - __bfloat162float(h3.y));
                aPh[0] = *(uint32_t*)&h0; aPh[1] = *(uint32_t*)&h1;
                aPh[2] = *(uint32_t*)&h2; aPh[3] = *(uint32_t*)&h3;
                aPl[0] = *(uint32_t*)&l0; aPl[1] = *(uint32_t*)&l1;
                aPl[2] = *(uint32_t*)&l2; aPl[3] = *(uint32_t*)&l3;
            }
#pragma unroll
            for (int nd = 0; nd < 8; nd++) {
                int row = nd * 8 + gq;
                uint32_t bh[2], bl[2];
                bh[0] = *(const uint32_t*)&sKh[row * AP + ko + kq];
                bh[1] = *(const uint32_t*)&sKh[row * AP + ko + kq + 8];
                bl[0] = *(const uint32_t*)&sKl[row * AP + ko + kq];
                bl[1] = *(const uint32_t*)&sKl[row * AP + ko + kq + 8];
                mma16816(O[nd], aPh, bh);
                mma16816(O[nd], aPh, bl);
                mma16816(O[nd], aPl, bh);
            }
        }
    }

    // ---- normalize + store ----
    float inv_a = 1.f / l_a, inv_b = 1.f / l_b;
#pragma unroll
    for (int nd = 0; nd < 8; nd++) {
        int col = h * HDz + nd * 8 + kq;
        float* da = y + (size_t)(b * Tz + ia) * Cz + col;
        *(float2*)da = make_float2(O[nd][0] * inv_a, O[nd][1] * inv_a);
        float* db = y + (size_t)(b * Tz + ib) * Cz + col;
        *(float2*)db = make_float2(O[nd][2] * inv_b, O[nd][3] * inv_b);
    }
}

// =========================================================================
// launcher
// =========================================================================
extern "C" void kernel_launch(void* const* d_in, const int* in_sizes, int n_in,
                              void* d_out, int out_size) {
    const float* x       = (const float*)d_in[0];
    const float* ln1_w   = (const float*)d_in[1];
    const float* w_attn  = (const float*)d_in[2];
    // d_in[3] = w_pos : dead code in the reference
    const float* w_cproj = (const float*)d_in[4];
    const float* ln2_w   = (const float*)d_in[5];
    const float* w_fc    = (const float*)d_in[6];
    const float* w_mproj = (const float*)d_in[7];
    float* out = (float*)d_out;

    float *h, *qtab, *y, *x1, *h2, *fc;
    __nv_bfloat16 *bth, *btl, *qkvh, *qkvl, *tabh, *tabl;
    cudaGetSymbolAddress((void**)&h, g_h);
    cudaGetSymbolAddress((void**)&qkvh, g_qkvh);
    cudaGetSymbolAddress((void**)&qkvl, g_qkvl);
    cudaGetSymbolAddress((void**)&tabh, g_tabh);
    cudaGetSymbolAddress((void**)&tabl, g_tabl);
    cudaGetSymbolAddress((void**)&qtab, g_qtab);
    cudaGetSymbolAddress((void**)&y, g_y);
    cudaGetSymbolAddress((void**)&x1, g_x1);
    cudaGetSymbolAddress((void**)&h2, g_h2);
    cudaGetSymbolAddress((void**)&fc, g_fc);
    cudaGetSymbolAddress((void**)&bth, g_bt_hi);
    cudaGetSymbolAddress((void**)&btl, g_bt_lo);

    // weight preprocessing
    k_tsplit<<<dim3(Cz / 32, (3 * Cz) / 32), 256>>>(w_attn, bth + WT_ATTN, btl + WT_ATTN, Cz, 3 * Cz);
    k_tsplit<<<dim3(Cz / 32, Cz / 32), 256>>>(w_cproj, bth + WT_CPROJ, btl + WT_CPROJ, Cz, Cz);
    k_tsplit<<<dim3(Cz / 32, (4 * Cz) / 32), 256>>>(w_fc, bth + WT_FC, btl + WT_FC, Cz, 4 * Cz);
    k_tsplit<<<dim3((4 * Cz) / 32, Cz / 32), 256>>>(w_mproj, bth + WT_MPROJ, btl + WT_MPROJ, 4 * Cz, Cz);

    k_tab<<<(Tz * HDz + 255) / 256, 256>>>(tabh, tabl);
    k_ln<<<BTz, 256>>>(x, ln1_w, h);

    // qkv = h @ w_attn -> bf16 hi/lo
    k_mma<3><<<dim3((3 * Cz) / 128, BTz / 128), 256>>>(
        h, bth + WT_ATTN, btl + WT_ATTN, nullptr, nullptr, qkvh, qkvl,
        BTz, 3 * Cz, Cz);
    // qtab (tensor core)
    k_qtabm<<<dim3(BHz, 16, 16), 128>>>(qkvh, qkvl, tabh, tabl, qtab);
    // fused attention (tensor core)
    k_attnm<<<dim3(BHz, 16), 128>>>(qkvh, qkvl, qtab, y);
    // x1 = x + y @ w_cproj
    k_mma<1><<<dim3(Cz / 128, BTz / 128), 256>>>(
        y, bth + WT_CPROJ, btl + WT_CPROJ, x, x1, nullptr, nullptr, BTz, Cz, Cz);
    // LN2
    k_ln<<<BTz, 256>>>(x1, ln2_w, h2);
    // fc = gelu(h2 @ w_fc)
    k_mma<2><<<dim3((4 * Cz) / 128, BTz / 128), 256>>>(
        h2, bth + WT_FC, btl + WT_FC, nullptr, fc, nullptr, nullptr,
        BTz, 4 * Cz, Cz);
    // out = x1 + fc @ w_mproj
    k_mma<1><<<dim3(Cz / 128, BTz / 128), 256>>>(
        fc, bth + WT_MPROJ, btl + WT_MPROJ, x1, out, nullptr, nullptr,
        BTz, Cz, 4 * Cz);
}